// round 15
// baseline (speedup 1.0000x reference)
#include <cuda_runtime.h>
#include <cuda_bf16.h>

// NeighborSearch_batch via 33x33 uniform grid.
// R6 query/splits kernels verbatim; binning = full-chip slotted scatter
// (measured 7.9us) + 16-CTA compaction into R6's dense layout.
// B=8, n=9225, m=4096, d=2, r=0.03.
// Output (float32): neighbors_index [B,m,64] then row_splits [B,m+1].

#define BATCH  8
#define NPTS   9225
#define NQ     4096
#define MAXN   64
#define GRID   33
#define NCELLS (GRID * GRID)
#define CAP    64     // per-query accept capacity (reference: observed max ~50)
#define SLOTC  48     // data slots/cell  (lambda 8.5; overflow P ~ 1e-11)
#define SLOTQ  32     // query slots/cell (lambda 3.8)

#define LPQ    4      // lanes per query
#define QPB    32     // queries per CTA
#define QTPB   (LPQ * QPB)   // 128 threads

// slotted staging (cursors re-zeroed at end of each run)
__device__ int    g_scnt  [BATCH * NCELLS];
__device__ int    g_sqcnt [BATCH * NCELLS];
__device__ float4 g_dslots[BATCH * NCELLS * SLOTC];
__device__ float4 g_qslots[BATCH * NCELLS * SLOTQ];
// dense layout consumed by the (R6-verbatim) query kernel
__device__ int    g_cnt_cell[BATCH * NCELLS];
__device__ int    g_start   [BATCH * NCELLS];
__device__ float4 g_pts     [BATCH * NPTS];   // (x, y, dn, idx-as-float-bits)
__device__ float4 g_qpts    [BATCH * NQ];     // (x, y, qn, idx-as-float-bits)
__device__ int    g_counts  [BATCH * NQ];

__device__ __forceinline__ int cell_of(float x, float y) {
    int cx = (int)(x * (float)GRID); if (cx > GRID - 1) cx = GRID - 1; if (cx < 0) cx = 0;
    int cy = (int)(y * (float)GRID); if (cy > GRID - 1) cy = GRID - 1; if (cy < 0) cy = 0;
    return cy * GRID + cx;
}

// ---- launch 1: full-chip slotted scatter (data + queries) ----
__global__ void scatter_kernel(const float* __restrict__ data,
                               const float* __restrict__ queries)
{
    const int gt = blockIdx.x * blockDim.x + threadIdx.x;
    if (gt < BATCH * NPTS) {
        const int b = gt / NPTS;
        const int j = gt - b * NPTS;
        const float2 p = ((const float2*)data)[gt];
        // dn = RN(RN(x*x) + RN(y*y))  (matches jnp.sum(data*data))
        const float nn = __fadd_rn(__fmul_rn(p.x, p.x), __fmul_rn(p.y, p.y));
        const int c = b * NCELLS + cell_of(p.x, p.y);
        const int pos = atomicAdd(&g_scnt[c], 1);
        if (pos < SLOTC)
            g_dslots[(size_t)c * SLOTC + pos] = make_float4(p.x, p.y, nn, __int_as_float(j));
    }
    if (gt < BATCH * NQ) {
        const int b = gt >> 12;
        const int j = gt & (NQ - 1);
        const float2 p = ((const float2*)queries)[gt];
        const float nn = __fadd_rn(__fmul_rn(p.x, p.x), __fmul_rn(p.y, p.y));
        const int c = b * NCELLS + cell_of(p.x, p.y);
        const int pos = atomicAdd(&g_sqcnt[c], 1);
        if (pos < SLOTQ)
            g_qslots[(size_t)c * SLOTQ + pos] = make_float4(p.x, p.y, nn, __int_as_float(j));
    }
}

// ---- launch 2: compact slots -> dense layout (one CTA per batch,kind) ----
// blocks 0..7: data; 8..15: queries. Scan slot counts, then warp-per-cell copy.
__global__ void __launch_bounds__(1024)
compact_kernel()
{
    __shared__ int s_start[NCELLS];
    __shared__ int warp_sums[32];

    const int isq = blockIdx.x >= BATCH;
    const int b   = blockIdx.x - (isq ? BATCH : 0);
    const int slotn = isq ? SLOTQ : SLOTC;
    const int* scnt = (isq ? g_sqcnt : g_scnt) + b * NCELLS;
    const float4* slots = isq ? (g_qslots + (size_t)b * NCELLS * SLOTQ)
                              : (g_dslots + (size_t)b * NCELLS * SLOTC);
    float4* dst = isq ? (g_qpts + (size_t)b * NQ)
                      : (g_pts  + (size_t)b * NPTS);

    const int t = threadIdx.x;
    const int lane = t & 31, wid = t >> 5;

    // exclusive scan over NCELLS=1089 clamped counts (2 elems/thread)
    const int i0 = 2 * t, i1 = 2 * t + 1;
    int c0 = 0, c1 = 0;
    if (i0 < NCELLS) { c0 = scnt[i0]; c0 = c0 < slotn ? c0 : slotn; }
    if (i1 < NCELLS) { c1 = scnt[i1]; c1 = c1 < slotn ? c1 : slotn; }
    const int total = c0 + c1;

    int x = total;
    #pragma unroll
    for (int o = 1; o < 32; o <<= 1) {
        int y = __shfl_up_sync(0xFFFFFFFFu, x, o);
        if (lane >= o) x += y;
    }
    if (lane == 31) warp_sums[wid] = x;
    __syncthreads();
    if (wid == 0) {
        int w = warp_sums[lane];
        #pragma unroll
        for (int o = 1; o < 32; o <<= 1) {
            int y = __shfl_up_sync(0xFFFFFFFFu, w, o);
            if (lane >= o) w += y;
        }
        warp_sums[lane] = w;
    }
    __syncthreads();

    const int excl = (x - total) + (wid > 0 ? warp_sums[wid - 1] : 0);
    if (i0 < NCELLS) {
        s_start[i0] = excl;
        if (!isq) { g_start[b * NCELLS + i0] = excl; g_cnt_cell[b * NCELLS + i0] = c0; }
    }
    if (i1 < NCELLS) {
        s_start[i1] = excl + c0;
        if (!isq) { g_start[b * NCELLS + i1] = excl + c0; g_cnt_cell[b * NCELLS + i1] = c1; }
    }
    __syncthreads();

    // warp-per-cell copy: lanes take slots in parallel (coalesced segments)
    for (int c = wid; c < NCELLS; c += 32) {
        int nc = scnt[c]; nc = nc < slotn ? nc : slotn;
        const float4* src = slots + (size_t)c * slotn;
        float4* d = dst + s_start[c];
        for (int s = lane; s < nc; s += 32) d[s] = src[s];
    }
}

// ---- launch 3: query kernel (R6 verbatim) ----
__global__ void __launch_bounds__(QTPB)
query_kernel(const float* __restrict__ radius,
             float* __restrict__ nbr_idx)
{
    __shared__ int cand[CAP][QPB + 1];   // stride 33: conflict-free

    const int tid   = threadIdx.x;
    const int sub   = tid & (LPQ - 1);        // 0..3 within group
    const int qslot = tid >> 2;               // 0..31 query slot in CTA
    const int shift = (tid & 31) & ~(LPQ - 1);
    const unsigned gmask = 0xFu << shift;

    const int b = blockIdx.y;
    const int qbin = blockIdx.x * QPB + qslot;

    const float4 qv = g_qpts[(size_t)b * NQ + qbin];  // 4-lane broadcast
    const float q0 = qv.x;
    const float q1 = qv.y;
    const float qn = qv.z;
    const int   oq = __float_as_int(qv.w);

    const float r  = radius[0];
    const float r2 = __fmul_rn(r, r);
    int reach = (int)ceilf(r * (float)GRID);
    if (reach < 1) reach = 1;

    int cx = (int)(q0 * (float)GRID); if (cx > GRID - 1) cx = GRID - 1; if (cx < 0) cx = 0;
    int cy = (int)(q1 * (float)GRID); if (cy > GRID - 1) cy = GRID - 1; if (cy < 0) cy = 0;
    const int x0 = max(0, cx - reach), x1 = min(GRID - 1, cx + reach);
    const int y0 = max(0, cy - reach), y1 = min(GRID - 1, cy + reach);

    const float4* pts = g_pts + (size_t)b * NPTS;
    const int* starts = g_start    + b * NCELLS;
    const int* cnts   = g_cnt_cell + b * NCELLS;

    int cnt = 0;

    for (int gy = y0; gy <= y1; ++gy) {
        const int ca = gy * GRID + x0;
        const int cb = gy * GRID + x1;
        const int s = starts[ca];
        const int e = starts[cb] + cnts[cb];
        // group-uniform trip count; lanes take i = ib+sub (coalesced 64B)
        for (int ib = s; ib < e; ib += LPQ) {
            const int i = ib + sub;
            bool acc = false;
            int idx = 0;
            if (i < e) {
                const float4 p = pts[i];
                // cross = RN(RN(q0*px) + RN(q1*py)); 2*cross exact (self-add)
                const float cr = __fadd_rn(__fmul_rn(q0, p.x), __fmul_rn(q1, p.y));
                // v = RN(RN(qn + dn) - 2*cross)
                const float v  = __fsub_rn(__fadd_rn(qn, p.z), __fadd_rn(cr, cr));
                acc = (v <= r2);
                idx = __float_as_int(p.w);
            }
            const unsigned bal = __ballot_sync(gmask, acc);
            const unsigned nib = (bal >> shift) & 0xFu;
            if (acc) {
                const int s2 = cnt + __popc(nib & ((1u << sub) - 1u));
                if (s2 < CAP) cand[s2][qslot] = idx;
            }
            cnt += __popc(nib);
        }
    }

    float* out = nbr_idx + ((size_t)(b * NQ + oq)) * MAXN;
    const int k = cnt < CAP ? cnt : CAP;

    // -1 fill (slots k..63), split across the 4 lanes
    for (int s = k + sub; s < MAXN; s += LPQ) out[s] = -1.0f;

    // rank-selection emit: rank_i = #{j : v_j < v_i} is a permutation of
    // 0..k-1 (indices distinct) -> sorted output, scatter-order independent.
    for (int i = sub; i < k; i += LPQ) {
        const int v = cand[i][qslot];
        int rank = 0;
        #pragma unroll 4
        for (int j = 0; j < k; ++j)
            rank += (cand[j][qslot] < v) ? 1 : 0;
        out[rank] = (float)v;   // rank <= k-1 < MAXN <= CAP
    }

    if (sub == 0) g_counts[b * NQ + oq] = cnt;
}

// ---- launch 4: row_splits (R6 verbatim) + slot-cursor reset ----
__global__ void __launch_bounds__(1024)
row_splits_kernel(float* __restrict__ row_splits)
{
    __shared__ int warp_sums[32];
    const int b = blockIdx.x;
    const int t = threadIdx.x;
    const int lane = t & 31, wid = t >> 5;

    // reset slot cursors for the next graph replay (8 CTAs cover 8712 ints)
    {
        const int i = b * 1024 + t;
        if (i < BATCH * NCELLS) { g_scnt[i] = 0; g_sqcnt[i] = 0; }
        const int i2 = i + BATCH * 1024;
        if (i2 < BATCH * NCELLS) { g_scnt[i2] = 0; g_sqcnt[i2] = 0; }
    }

    const int* c = g_counts + b * NQ;
    const int base = t * 4;
    const int c0 = c[base + 0], c1 = c[base + 1], c2 = c[base + 2], c3 = c[base + 3];
    const int s0 = c0, s1 = s0 + c1, s2 = s1 + c2, s3 = s2 + c3;
    const int total = s3;

    int x = total;
    #pragma unroll
    for (int o = 1; o < 32; o <<= 1) {
        int y = __shfl_up_sync(0xFFFFFFFFu, x, o);
        if (lane >= o) x += y;
    }
    if (lane == 31) warp_sums[wid] = x;
    __syncthreads();
    if (wid == 0) {
        int w = warp_sums[lane];
        #pragma unroll
        for (int o = 1; o < 32; o <<= 1) {
            int y = __shfl_up_sync(0xFFFFFFFFu, w, o);
            if (lane >= o) w += y;
        }
        warp_sums[lane] = w;
    }
    __syncthreads();

    const int excl = (x - total) + (wid > 0 ? warp_sums[wid - 1] : 0);
    float* rs = row_splits + b * (NQ + 1);
    if (t == 0) rs[0] = 0.0f;
    rs[base + 1] = (float)(excl + s0);
    rs[base + 2] = (float)(excl + s1);
    rs[base + 3] = (float)(excl + s2);
    rs[base + 4] = (float)(excl + s3);
}

extern "C" void kernel_launch(void* const* d_in, const int* in_sizes, int n_in,
                              void* d_out, int out_size)
{
    const float* data    = (const float*)d_in[0];   // [8, 9225, 2]
    const float* queries = (const float*)d_in[1];   // [8, 4096, 2]
    const float* radius  = (const float*)d_in[2];   // scalar

    float* nbr_idx    = (float*)d_out;                          // [8, 4096, 64]
    float* row_splits = nbr_idx + (size_t)BATCH * NQ * MAXN;    // [8, 4097]

    scatter_kernel<<<(BATCH * NPTS + 255) / 256, 256>>>(data, queries);
    compact_kernel<<<2 * BATCH, 1024>>>();

    dim3 qgrid(NQ / QPB, BATCH);
    query_kernel<<<qgrid, QTPB>>>(radius, nbr_idx);
    row_splits_kernel<<<BATCH, 1024>>>(row_splits);
}

// round 16
// speedup vs baseline: 1.4204x; 1.4204x over previous
#include <cuda_runtime.h>
#include <cuda_bf16.h>

// NeighborSearch_batch via 33x33 uniform grid — R6 query/row_splits kernels
// VERBATIM; bin_kernel rebuilt: one atomic pass (saved ranks) and data
// binning split 3-ways by cell row (per-third dense regions, base embedded
// in g_start so the query kernel is unchanged).
// B=8, n=9225, m=4096, d=2, r=0.03.
// Output (float32): neighbors_index [B,m,64] then row_splits [B,m+1].

#define BATCH  8
#define NPTS   9225
#define NQ     4096
#define MAXN   64
#define GRID   33
#define NCELLS (GRID * GRID)      // 1089
#define CAP    64                 // per-query accept cap (observed max ~50)

#define DSPLIT 3                  // data thirds per batch (by gy)
#define GYS    11                 // 33/3 rows per third
#define NCOWN  (GYS * GRID)       // 363 cells per third
#define CAPH   4096               // per-third point capacity (mean 3075, 22sigma)
#define PER_B  (DSPLIT + 1)       // CTAs per batch in bin_kernel

#define LPQ    4                  // lanes per query
#define QPB    32                 // queries per CTA
#define QTPB   (LPQ * QPB)        // 128 threads

__device__ int    g_cnt_cell[BATCH * NCELLS];
__device__ int    g_start   [BATCH * NCELLS];
__device__ float4 g_pts     [BATCH * DSPLIT * CAPH]; // per-third dense regions
__device__ float4 g_qpts    [BATCH * NQ];            // dense, cell-sorted
__device__ int    g_counts  [BATCH * NQ];

__device__ __forceinline__ int cell_of(float x, float y) {
    int cx = (int)(x * (float)GRID); if (cx > GRID - 1) cx = GRID - 1; if (cx < 0) cx = 0;
    int cy = (int)(y * (float)GRID); if (cy > GRID - 1) cy = GRID - 1; if (cy < 0) cy = 0;
    return cy * GRID + cx;
}

// 32 CTAs: batch b = blockIdx.x/4; part 0..2 = data third, part 3 = queries.
// Pass 1: count own cells (smem atomics), SAVING each point's within-cell
// rank in registers. Scan. Pass 2: place points (no atomics).
__global__ void __launch_bounds__(1024)
bin_kernel(const float* __restrict__ data,
           const float* __restrict__ queries)
{
    __shared__ int scnt  [NCELLS];
    __shared__ int sstart[NCELLS];
    __shared__ int warp_sums[32];

    const int b    = blockIdx.x / PER_B;
    const int part = blockIdx.x - b * PER_B;
    const bool isq = (part == DSPLIT);

    const int n     = isq ? NQ : NPTS;
    const int cbase = isq ? 0 : part * NCOWN;     // contiguous cell range
    const int nown  = isq ? NCELLS : NCOWN;
    const float2* src = isq ? ((const float2*)queries + (size_t)b * NQ)
                            : ((const float2*)data    + (size_t)b * NPTS);

    const int t = threadIdx.x;
    const int lane = t & 31, wid = t >> 5;

    for (int i = t; i < nown; i += 1024) scnt[i] = 0;
    __syncthreads();

    // ---- pass 1: count (one atomic per owned point; rank saved) ----
    int pos[10];
    int rel[10];
    if (isq) {
        #pragma unroll
        for (int it = 0; it < 4; ++it) {
            const int i = t + it * 1024;
            rel[it] = -1;
            if (i < NQ) {
                const float2 p = src[i];
                rel[it] = cell_of(p.x, p.y);          // cbase = 0
                pos[it] = atomicAdd(&scnt[rel[it]], 1);
            }
        }
    } else {
        #pragma unroll
        for (int it = 0; it < 10; ++it) {
            const int i = t + it * 1024;
            rel[it] = -1;
            if (i < NPTS) {
                const float2 p = src[i];
                const int rc = cell_of(p.x, p.y) - cbase;
                if (rc >= 0 && rc < NCOWN) {
                    rel[it] = rc;
                    pos[it] = atomicAdd(&scnt[rc], 1);
                }
            }
        }
    }
    __syncthreads();

    // ---- exclusive scan over nown counts (2 elems/thread) ----
    const int i0 = 2 * t, i1 = 2 * t + 1;
    const int c0 = (i0 < nown) ? scnt[i0] : 0;
    const int c1 = (i1 < nown) ? scnt[i1] : 0;
    const int total = c0 + c1;

    int x = total;
    #pragma unroll
    for (int o = 1; o < 32; o <<= 1) {
        int y = __shfl_up_sync(0xFFFFFFFFu, x, o);
        if (lane >= o) x += y;
    }
    if (lane == 31) warp_sums[wid] = x;
    __syncthreads();
    if (wid == 0) {
        int w = warp_sums[lane];
        #pragma unroll
        for (int o = 1; o < 32; o <<= 1) {
            int y = __shfl_up_sync(0xFFFFFFFFu, w, o);
            if (lane >= o) w += y;
        }
        warp_sums[lane] = w;
    }
    __syncthreads();

    const int excl = (x - total) + (wid > 0 ? warp_sums[wid - 1] : 0);
    if (i0 < nown) {
        sstart[i0] = excl;
        if (!isq) {
            g_start[b * NCELLS + cbase + i0]    = excl + part * CAPH;
            g_cnt_cell[b * NCELLS + cbase + i0] = c0;
        }
    }
    if (i1 < nown) {
        sstart[i1] = excl + c0;
        if (!isq) {
            g_start[b * NCELLS + cbase + i1]    = excl + c0 + part * CAPH;
            g_cnt_cell[b * NCELLS + cbase + i1] = c1;
        }
    }
    __syncthreads();

    // ---- pass 2: place points (no atomics; reload via L1) ----
    // nn = RN(RN(x*x) + RN(y*y))  (matches jnp.sum(v*v, axis=-1))
    float4* dst = isq ? (g_qpts + (size_t)b * NQ)
                      : (g_pts + (size_t)(b * DSPLIT + part) * CAPH);
    if (isq) {
        #pragma unroll
        for (int it = 0; it < 4; ++it) {
            if (rel[it] >= 0) {
                const int i = t + it * 1024;
                const float2 p = src[i];
                const float nn = __fadd_rn(__fmul_rn(p.x, p.x), __fmul_rn(p.y, p.y));
                dst[sstart[rel[it]] + pos[it]] =
                    make_float4(p.x, p.y, nn, __int_as_float(i));
            }
        }
    } else {
        #pragma unroll
        for (int it = 0; it < 10; ++it) {
            if (rel[it] >= 0) {
                const int i = t + it * 1024;
                const float2 p = src[i];
                const float nn = __fadd_rn(__fmul_rn(p.x, p.x), __fmul_rn(p.y, p.y));
                dst[sstart[rel[it]] + pos[it]] =
                    make_float4(p.x, p.y, nn, __int_as_float(i));
            }
        }
    }
}

// ---- query kernel (R6 verbatim) ----
__global__ void __launch_bounds__(QTPB)
query_kernel(const float* __restrict__ radius,
             float* __restrict__ nbr_idx)
{
    __shared__ int cand[CAP][QPB + 1];   // stride 33: conflict-free

    const int tid   = threadIdx.x;
    const int sub   = tid & (LPQ - 1);        // 0..3 within group
    const int qslot = tid >> 2;               // 0..31 query slot in CTA
    const int shift = (tid & 31) & ~(LPQ - 1);
    const unsigned gmask = 0xFu << shift;

    const int b = blockIdx.y;
    const int qbin = blockIdx.x * QPB + qslot;

    const float4 qv = g_qpts[(size_t)b * NQ + qbin];  // 4-lane broadcast
    const float q0 = qv.x;
    const float q1 = qv.y;
    const float qn = qv.z;
    const int   oq = __float_as_int(qv.w);

    const float r  = radius[0];
    const float r2 = __fmul_rn(r, r);
    int reach = (int)ceilf(r * (float)GRID);
    if (reach < 1) reach = 1;

    int cx = (int)(q0 * (float)GRID); if (cx > GRID - 1) cx = GRID - 1; if (cx < 0) cx = 0;
    int cy = (int)(q1 * (float)GRID); if (cy > GRID - 1) cy = GRID - 1; if (cy < 0) cy = 0;
    const int x0 = max(0, cx - reach), x1 = min(GRID - 1, cx + reach);
    const int y0 = max(0, cy - reach), y1 = min(GRID - 1, cy + reach);

    const float4* pts = g_pts + (size_t)b * DSPLIT * CAPH;
    const int* starts = g_start    + b * NCELLS;
    const int* cnts   = g_cnt_cell + b * NCELLS;

    int cnt = 0;

    for (int gy = y0; gy <= y1; ++gy) {
        const int ca = gy * GRID + x0;
        const int cb = gy * GRID + x1;
        const int s = starts[ca];
        const int e = starts[cb] + cnts[cb];
        // group-uniform trip count; lanes take i = ib+sub (coalesced 64B)
        for (int ib = s; ib < e; ib += LPQ) {
            const int i = ib + sub;
            bool acc = false;
            int idx = 0;
            if (i < e) {
                const float4 p = pts[i];
                // cross = RN(RN(q0*px) + RN(q1*py)); 2*cross exact (self-add)
                const float cr = __fadd_rn(__fmul_rn(q0, p.x), __fmul_rn(q1, p.y));
                // v = RN(RN(qn + dn) - 2*cross)
                const float v  = __fsub_rn(__fadd_rn(qn, p.z), __fadd_rn(cr, cr));
                acc = (v <= r2);
                idx = __float_as_int(p.w);
            }
            const unsigned bal = __ballot_sync(gmask, acc);
            const unsigned nib = (bal >> shift) & 0xFu;
            if (acc) {
                const int s2 = cnt + __popc(nib & ((1u << sub) - 1u));
                if (s2 < CAP) cand[s2][qslot] = idx;
            }
            cnt += __popc(nib);
        }
    }

    float* out = nbr_idx + ((size_t)(b * NQ + oq)) * MAXN;
    const int k = cnt < CAP ? cnt : CAP;

    // -1 fill (slots k..63), split across the 4 lanes
    for (int s = k + sub; s < MAXN; s += LPQ) out[s] = -1.0f;

    // rank-selection emit: rank_i = #{j : v_j < v_i} is a permutation of
    // 0..k-1 (indices distinct) -> sorted output, scatter-order independent.
    for (int i = sub; i < k; i += LPQ) {
        const int v = cand[i][qslot];
        int rank = 0;
        #pragma unroll 4
        for (int j = 0; j < k; ++j)
            rank += (cand[j][qslot] < v) ? 1 : 0;
        out[rank] = (float)v;   // rank <= k-1 < MAXN <= CAP
    }

    if (sub == 0) g_counts[b * NQ + oq] = cnt;
}

// ---- row_splits (R6 verbatim) ----
__global__ void __launch_bounds__(1024)
row_splits_kernel(float* __restrict__ row_splits)
{
    __shared__ int warp_sums[32];
    const int b = blockIdx.x;
    const int t = threadIdx.x;
    const int lane = t & 31, wid = t >> 5;

    const int* c = g_counts + b * NQ;
    const int base = t * 4;
    const int c0 = c[base + 0], c1 = c[base + 1], c2 = c[base + 2], c3 = c[base + 3];
    const int s0 = c0, s1 = s0 + c1, s2 = s1 + c2, s3 = s2 + c3;
    const int total = s3;

    int x = total;
    #pragma unroll
    for (int o = 1; o < 32; o <<= 1) {
        int y = __shfl_up_sync(0xFFFFFFFFu, x, o);
        if (lane >= o) x += y;
    }
    if (lane == 31) warp_sums[wid] = x;
    __syncthreads();
    if (wid == 0) {
        int w = warp_sums[lane];
        #pragma unroll
        for (int o = 1; o < 32; o <<= 1) {
            int y = __shfl_up_sync(0xFFFFFFFFu, w, o);
            if (lane >= o) w += y;
        }
        warp_sums[lane] = w;
    }
    __syncthreads();

    const int excl = (x - total) + (wid > 0 ? warp_sums[wid - 1] : 0);
    float* rs = row_splits + b * (NQ + 1);
    if (t == 0) rs[0] = 0.0f;
    rs[base + 1] = (float)(excl + s0);
    rs[base + 2] = (float)(excl + s1);
    rs[base + 3] = (float)(excl + s2);
    rs[base + 4] = (float)(excl + s3);
}

extern "C" void kernel_launch(void* const* d_in, const int* in_sizes, int n_in,
                              void* d_out, int out_size)
{
    const float* data    = (const float*)d_in[0];   // [8, 9225, 2]
    const float* queries = (const float*)d_in[1];   // [8, 4096, 2]
    const float* radius  = (const float*)d_in[2];   // scalar

    float* nbr_idx    = (float*)d_out;                          // [8, 4096, 64]
    float* row_splits = nbr_idx + (size_t)BATCH * NQ * MAXN;    // [8, 4097]

    bin_kernel<<<BATCH * PER_B, 1024>>>(data, queries);

    dim3 qgrid(NQ / QPB, BATCH);
    query_kernel<<<qgrid, QTPB>>>(radius, nbr_idx);
    row_splits_kernel<<<BATCH, 1024>>>(row_splits);
}